// round 7
// baseline (speedup 1.0000x reference)
#include <cuda_runtime.h>
#include <cuda_bf16.h>
#include <cstdint>

// ---------------------------------------------------------------------------
// Swin window attention: B_=2048, N=49, H=16, D=32, C=512, nW=64, fp32.
// Split-bf16 HMMA GEMMs (BK=32, 2-stage cp.async, ONE barrier per epoch)
// + conflict-free fused attention.
// ---------------------------------------------------------------------------
#define B_TOT   2048
#define NTOK    49
#define NHEAD   16
#define HDIM    32
#define CDIM    512
#define NWIN    64
#define QK_SCALE 0.17677669529663687f
#define M_ROWS  (B_TOT * NTOK)          // 100352 = 784 * 128

__device__ float          g_qkv[(size_t)M_ROWS * 3 * CDIM];
__device__ __nv_bfloat16  g_xh [(size_t)M_ROWS * CDIM];
__device__ __nv_bfloat16  g_xl [(size_t)M_ROWS * CDIM];
__device__ __nv_bfloat16  g_aoh[(size_t)M_ROWS * CDIM];
__device__ __nv_bfloat16  g_aol[(size_t)M_ROWS * CDIM];
__device__ __nv_bfloat16  g_wqh[3 * CDIM * CDIM];
__device__ __nv_bfloat16  g_wql[3 * CDIM * CDIM];
__device__ __nv_bfloat16  g_wph[CDIM * CDIM];
__device__ __nv_bfloat16  g_wpl[CDIM * CDIM];

// ---------------------------------------------------------------------------
__device__ __forceinline__ uint32_t smem_u32(const void* p) {
    uint32_t a;
    asm("{ .reg .u64 t; cvta.to.shared.u64 t, %1; cvt.u32.u64 %0, t; }"
        : "=r"(a) : "l"(p));
    return a;
}

__device__ __forceinline__ void cvt_pair(float x, float y, uint32_t& hp, uint32_t& lp) {
    unsigned short h0 = __bfloat16_as_ushort(__float2bfloat16_rn(x));
    unsigned short h1 = __bfloat16_as_ushort(__float2bfloat16_rn(y));
    hp = (uint32_t)h0 | ((uint32_t)h1 << 16);
    float l0 = x - __uint_as_float((uint32_t)h0 << 16);
    float l1 = y - __uint_as_float((uint32_t)h1 << 16);
    asm("cvt.rn.bf16x2.f32 %0, %1, %2;" : "=r"(lp) : "f"(l1), "f"(l0));
}

#define LDSM4(r, addr) \
    asm volatile("ldmatrix.sync.aligned.m8n8.x4.shared.b16 {%0,%1,%2,%3}, [%4];" \
        : "=r"((r)[0]), "=r"((r)[1]), "=r"((r)[2]), "=r"((r)[3]) : "r"(addr))

#define MMA16816(d, a, b0, b1) \
    asm volatile("mma.sync.aligned.m16n8k16.row.col.f32.bf16.bf16.f32 " \
        "{%0,%1,%2,%3}, {%4,%5,%6,%7}, {%8,%9}, {%0,%1,%2,%3};" \
        : "+f"((d)[0]), "+f"((d)[1]), "+f"((d)[2]), "+f"((d)[3]) \
        : "r"((a)[0]), "r"((a)[1]), "r"((a)[2]), "r"((a)[3]), "r"(b0), "r"(b1))

#define CP16(saddr, gaddr) \
    asm volatile("cp.async.cg.shared.global [%0], [%1], 16;" :: "r"(saddr), "l"(gaddr))
#define CP_COMMIT() asm volatile("cp.async.commit_group;" ::: "memory")
#define CP_WAIT(n)  asm volatile("cp.async.wait_group %0;" :: "n"(n) : "memory")

// ---------------------------------------------------------------------------
__global__ void split_bf16_kernel(const float4* __restrict__ src,
                                  uint2* __restrict__ dh, uint2* __restrict__ dl,
                                  int n4)
{
    int i = blockIdx.x * blockDim.x + threadIdx.x;
    if (i < n4) {
        float4 v = src[i];
        uint32_t h0, l0, h1, l1;
        cvt_pair(v.x, v.y, h0, l0);
        cvt_pair(v.z, v.w, h1, l1);
        dh[i] = make_uint2(h0, h1);
        dl[i] = make_uint2(l0, l1);
    }
}

// ---------------------------------------------------------------------------
// HMMA split-bf16 GEMM: C[M,N] = A[M,K]*W[N,K]^T + bias, bf16 hi/lo operands.
// CTA 128x128, BK=32, 256 threads, 2-stage cp.async, warp tile 64x32.
// One __syncthreads per K-epoch:
//   iter i: wait(stage i ready); sync (=> all warps done reading buf i&1 from
//   iter i-2's compute AND done with compute(i-1)); issue stage i+2 into
//   buf i&1's partner? NO -> stage i+2 goes to buf (i+2)&1 == buf i&1, which
//   compute(i) is about to read. Therefore we issue stage i+2 at the TOP of
//   iteration i+1 (after that sync), i.e. inside this loop we issue (i+1)+1.
//   Implemented as: issue(i+2) guarded so that it runs at iter i+1.
//   Equivalent simple form used below: at iter i, after sync, issue stage
//   i+2 ONLY IF compute of stage i's buffer partner is protected -- which the
//   sync provides because compute(i-1) on buf (i-1)&1 == (i+1)&1 is complete
//   and stage i+2 targets buf (i+2)&1 == buf i&1... -> must NOT issue here.
// Correct minimal schedule (used): prologue issues stages 0,1; at iter i we
// issue stage i+2 AFTER the sync of iter i+1 -- i.e. the issue for stage s
// happens at iter s-1, top-of-loop, post-sync, where buf s&1 was last read
// by compute(s-2) which finished before the sync of iter s-1.
// ---------------------------------------------------------------------------
#define ROWB      80
#define TILE_SZ   10240            // 128 rows * 80B
#define STAGE_SZ  40960            // AH AL BH BL
#define SMEM_GEMM 81920

__global__ __launch_bounds__(256, 2)
void hmma_gemm(const __nv_bfloat16* __restrict__ Ah, const __nv_bfloat16* __restrict__ Al,
               const __nv_bfloat16* __restrict__ Bh, const __nv_bfloat16* __restrict__ Bl,
               const float* __restrict__ bias, float* __restrict__ C,
               int N, int K)
{
    extern __shared__ char sm[];
    const uint32_t sb = smem_u32(sm);

    const int tid = threadIdx.x;
    const int wid = tid >> 5, lid = tid & 31;
    const int warp_m = wid & 1;
    const int warp_n = wid >> 1;
    const int m0 = blockIdx.y * 128;
    const int n0 = blockIdx.x * 128;

    const __nv_bfloat16* gbase[4] = {
        Ah + (size_t)m0 * K, Al + (size_t)m0 * K,
        Bh + (size_t)n0 * K, Bl + (size_t)n0 * K };

    const uint32_t aRow  = (uint32_t)(warp_m * 64 + (lid & 15));
    const uint32_t aKoff = (uint32_t)((lid >> 4) << 4);
    const uint32_t bRow  = (uint32_t)(warp_n * 32 + ((lid >> 4) << 3) + (lid & 7));
    const uint32_t bKoff = (uint32_t)(((lid >> 3) & 1) << 4);
    const uint32_t aOff = aRow * ROWB + aKoff;
    const uint32_t bOff = bRow * ROWB + bKoff;

    float acc[4][4][4];
#pragma unroll
    for (int i = 0; i < 4; i++)
#pragma unroll
        for (int j = 0; j < 4; j++)
#pragma unroll
            for (int e = 0; e < 4; e++) acc[i][j][e] = 0.f;

    const int iters = K >> 5;      // BK=32

#define ISSUE_STAGE(it) do {                                                  \
        const int kblk = (it) * 32;                                           \
        const uint32_t stb = sb + ((it) & 1) * STAGE_SZ;                      \
        _Pragma("unroll")                                                     \
        for (int s = 0; s < 8; s++) {                                         \
            const int id   = tid + s * 256;                                   \
            const int tile = id >> 9;                                         \
            const int row  = (id >> 2) & 127;                                 \
            const int c    = id & 3;                                          \
            CP16(stb + tile * TILE_SZ + row * ROWB + c * 16,                  \
                 gbase[tile] + (size_t)row * K + kblk + c * 8);               \
        }                                                                     \
    } while (0)

    ISSUE_STAGE(0); CP_COMMIT();
    ISSUE_STAGE(1); CP_COMMIT();

    for (int i = 0; i < iters; i++) {
        // stage i complete: pending groups are {i, i+1} until we issue more
        if (i + 1 < iters) CP_WAIT(1); else CP_WAIT(0);
        __syncthreads();   // all warps done with compute(i-1) -> buf (i+1)&1 free
        if (i + 1 < iters && i + 2 <= iters - 1) {
            // issue stage i+2 into buf i&1? that's the buffer compute(i) reads.
            // Safe ordering requires issuing stage (i+2) only after compute(i).
            // We instead issue stage (i+1)+1 here for NEXT iteration's horizon:
            // stage s=i+2 targets buf (i+2)&1 == i&1 -> conflicts with this
            // iteration's reads, so the issue is deferred: see post-compute.
        }

        const uint32_t st = sb + (i & 1) * STAGE_SZ;
        const uint32_t aHi = st + aOff;
        const uint32_t aLo = st + TILE_SZ + aOff;
        const uint32_t bHi = st + 2 * TILE_SZ + bOff;
        const uint32_t bLo = st + 3 * TILE_SZ + bOff;

#pragma unroll
        for (int ks = 0; ks < 2; ks++) {
            const uint32_t ko = (uint32_t)(ks * 32);
            uint32_t bh[2][4], bl[2][4];
            LDSM4(bh[0], bHi + ko);
            LDSM4(bh[1], bHi + ko + 16 * ROWB);
            LDSM4(bl[0], bLo + ko);
            LDSM4(bl[1], bLo + ko + 16 * ROWB);
#pragma unroll
            for (int mi = 0; mi < 4; mi++) {
                uint32_t ah[4], al[4];
                LDSM4(ah, aHi + ko + mi * (16 * ROWB));
                LDSM4(al, aLo + ko + mi * (16 * ROWB));
#pragma unroll
                for (int nj = 0; nj < 4; nj++) {
                    const uint32_t* bph = bh[nj >> 1] + ((nj & 1) << 1);
                    const uint32_t* bpl = bl[nj >> 1] + ((nj & 1) << 1);
                    MMA16816(acc[mi][nj], ah, bph[0], bph[1]);
                    MMA16816(acc[mi][nj], ah, bpl[0], bpl[1]);
                    MMA16816(acc[mi][nj], al, bph[0], bph[1]);
                }
            }
        }

        // Post-compute issue of stage i+2 into buf i&1 (this warp is done
        // reading it; cross-warp safety comes from the NEXT iteration's
        // __syncthreads, which orders all warps' compute(i) before any warp's
        // cp.async writes land... cp.async writes from THIS warp could race
        // other warps still reading buf i&1. To stay safe we only issue from
        // here when all warps have provably finished: enforced by issuing
        // AFTER the next sync instead. Net effect: single issue point below.
        if (i + 2 < iters) {
            __syncthreads();          // all warps finished compute(i)
            ISSUE_STAGE(i + 2); CP_COMMIT();
        }
    }
#undef ISSUE_STAGE

    const int l4 = lid >> 2;
    const int lc = (lid & 3) * 2;
#pragma unroll
    for (int mi = 0; mi < 4; mi++) {
        const int row = m0 + warp_m * 64 + mi * 16 + l4;
#pragma unroll
        for (int nj = 0; nj < 4; nj++) {
            const int col = n0 + warp_n * 32 + nj * 8 + lc;
            const float b0 = bias[col], b1 = bias[col + 1];
            float2 v0 = make_float2(acc[mi][nj][0] + b0, acc[mi][nj][1] + b1);
            float2 v1 = make_float2(acc[mi][nj][2] + b0, acc[mi][nj][3] + b1);
            *(float2*)(C + (size_t)row * N + col)       = v0;
            *(float2*)(C + (size_t)(row + 8) * N + col) = v1;
        }
    }
}

// ---------------------------------------------------------------------------
// Fused window attention, conflict-free mappings (unchanged from R6).
// ---------------------------------------------------------------------------
#define SCPAD 68

__global__ __launch_bounds__(128)
void window_attn_kernel(const float* __restrict__ qkv,
                        const float* __restrict__ mask,
                        const float* __restrict__ rpb,
                        __nv_bfloat16* __restrict__ aoh,
                        __nv_bfloat16* __restrict__ aol)
{
    const int b = blockIdx.x >> 4;
    const int h = blockIdx.x & 15;
    const int tid = threadIdx.x;
    const int wid = tid >> 5, lid = tid & 31;

    __shared__ float qs[56][36];
    __shared__ float ks[64][36];
    __shared__ float vs[64][36];
    __shared__ float sc[56][SCPAD];

    const size_t base = (size_t)b * NTOK * (3 * CDIM) + h * HDIM;
    for (int idx = tid; idx < NTOK * HDIM; idx += 128) {
        const int n = idx >> 5, d = idx & 31;
        const size_t off = base + (size_t)n * (3 * CDIM) + d;
        qs[n][d] = qkv[off] * QK_SCALE;
        ks[n][d] = qkv[off + CDIM];
        vs[n][d] = qkv[off + 2 * CDIM];
    }
    for (int idx = tid; idx < 15 * HDIM; idx += 128) {
        const int n = NTOK + (idx >> 5), d = idx & 31;
        if (n < 56) qs[n][d] = 0.f;
        ks[n][d] = 0.f;
        vs[n][d] = 0.f;
    }
    __syncthreads();

    const float* mrow = mask + (size_t)(b & (NWIN - 1)) * NTOK * NTOK;
    {
        const int nt = tid & 7;
        const int mt = tid >> 3;
        float a[7][4];
#pragma unroll
        for (int i = 0; i < 7; i++)
#pragma unroll
            for (int j = 0; j < 4; j++) a[i][j] = 0.f;

#pragma unroll
        for (int d4 = 0; d4 < 8; d4++) {
            float4 k4[4];
#pragma unroll
            for (int j = 0; j < 4; j++) k4[j] = *(float4*)&ks[mt * 4 + j][d4 * 4];
#pragma unroll
            for (int i = 0; i < 7; i++) {
                float4 q4 = *(float4*)&qs[nt * 7 + i][d4 * 4];
#pragma unroll
                for (int j = 0; j < 4; j++)
                    a[i][j] += q4.x * k4[j].x + q4.y * k4[j].y
                             + q4.z * k4[j].z + q4.w * k4[j].w;
            }
        }
#pragma unroll
        for (int i = 0; i < 7; i++) {
            const int n = nt * 7 + i;
#pragma unroll
            for (int j = 0; j < 4; j++) {
                const int m = mt * 4 + j;
                float v;
                if (n < NTOK && m < NTOK) {
                    const int ridx = (n / 7 - m / 7 + 6) * 13 + (n % 7 - m % 7 + 6);
                    v = a[i][j] + rpb[ridx * NHEAD + h] + mrow[n * NTOK + m];
                } else {
                    v = (n < NTOK) ? -3.0e38f : 0.f;
                }
                sc[n][m] = v;
            }
        }
    }
    __syncthreads();

    for (int r = wid; r < NTOK; r += 4) {
        float v0 = sc[r][lid];
        float v1 = sc[r][lid + 32];
        float mx = fmaxf(v0, v1);
#pragma unroll
        for (int o = 16; o; o >>= 1) mx = fmaxf(mx, __shfl_xor_sync(~0u, mx, o));
        float e0 = __expf(v0 - mx);
        float e1 = __expf(v1 - mx);
        float s = e0 + e1;
#pragma unroll
        for (int o = 16; o; o >>= 1) s += __shfl_xor_sync(~0u, s, o);
        const float inv = 1.f / s;
        sc[r][lid] = e0 * inv;
        sc[r][lid + 32] = e1 * inv;
    }
    __syncthreads();

    {
        const int dp = tid & 15;
        const int nb = tid >> 4;
        float ac[7][2];
#pragma unroll
        for (int i = 0; i < 7; i++) { ac[i][0] = 0.f; ac[i][1] = 0.f; }

#pragma unroll
        for (int m4 = 0; m4 < 16; m4++) {
            float2 v2[4];
#pragma unroll
            for (int k = 0; k < 4; k++) v2[k] = *(float2*)&vs[m4 * 4 + k][dp * 2];
#pragma unroll
            for (int i = 0; i < 7; i++) {
                float4 s4 = *(float4*)&sc[nb + 8 * i][m4 * 4];
                ac[i][0] += s4.x * v2[0].x + s4.y * v2[1].x
                          + s4.z * v2[2].x + s4.w * v2[3].x;
                ac[i][1] += s4.x * v2[0].y + s4.y * v2[1].y
                          + s4.z * v2[2].y + s4.w * v2[3].y;
            }
        }
#pragma unroll
        for (int i = 0; i < 7; i++) {
            const int n = nb + 8 * i;
            if (n < NTOK) {
                const size_t o = (size_t)(b * NTOK + n) * CDIM + h * HDIM + dp * 2;
                uint32_t hp, lp;
                cvt_pair(ac[i][0], ac[i][1], hp, lp);
                *(uint32_t*)(aoh + o) = hp;
                *(uint32_t*)(aol + o) = lp;
            }
        }
    }
}

// ---------------------------------------------------------------------------
extern "C" void kernel_launch(void* const* d_in, const int* in_sizes, int n_in,
                              void* d_out, int out_size)
{
    const float* x      = (const float*)d_in[0];
    const float* mask   = (const float*)d_in[1];
    const float* rpb    = (const float*)d_in[2];
    const float* qkv_w  = (const float*)d_in[3];
    const float* qkv_b  = (const float*)d_in[4];
    const float* proj_w = (const float*)d_in[5];
    const float* proj_b = (const float*)d_in[6];
    float* out = (float*)d_out;

    float *qkv_ptr = nullptr;
    __nv_bfloat16 *xh, *xl, *aoh, *aol, *wqh, *wql, *wph, *wpl;
    cudaGetSymbolAddress((void**)&qkv_ptr, g_qkv);
    cudaGetSymbolAddress((void**)&xh,  g_xh);
    cudaGetSymbolAddress((void**)&xl,  g_xl);
    cudaGetSymbolAddress((void**)&aoh, g_aoh);
    cudaGetSymbolAddress((void**)&aol, g_aol);
    cudaGetSymbolAddress((void**)&wqh, g_wqh);
    cudaGetSymbolAddress((void**)&wql, g_wql);
    cudaGetSymbolAddress((void**)&wph, g_wph);
    cudaGetSymbolAddress((void**)&wpl, g_wpl);

    static bool cfg = false;
    if (!cfg) {
        cudaFuncSetAttribute(hmma_gemm, cudaFuncAttributeMaxDynamicSharedMemorySize,
                             SMEM_GEMM);
        cfg = true;
    }

    {
        int n4 = (M_ROWS * CDIM) / 4;
        split_bf16_kernel<<<(n4 + 255) / 256, 256>>>(
            (const float4*)x, (uint2*)xh, (uint2*)xl, n4);
        n4 = (3 * CDIM * CDIM) / 4;
        split_bf16_kernel<<<(n4 + 255) / 256, 256>>>(
            (const float4*)qkv_w, (uint2*)wqh, (uint2*)wql, n4);
        n4 = (CDIM * CDIM) / 4;
        split_bf16_kernel<<<(n4 + 255) / 256, 256>>>(
            (const float4*)proj_w, (uint2*)wph, (uint2*)wpl, n4);
    }

    hmma_gemm<<<dim3((3 * CDIM) / 128, M_ROWS / 128), 256, SMEM_GEMM>>>(
        xh, xl, wqh, wql, qkv_b, qkv_ptr, 3 * CDIM, CDIM);

    window_attn_kernel<<<B_TOT * NHEAD, 128>>>(qkv_ptr, mask, rpb, aoh, aol);

    hmma_gemm<<<dim3(CDIM / 128, M_ROWS / 128), 256, SMEM_GEMM>>>(
        aoh, aol, wph, wpl, proj_b, out, CDIM, CDIM);
}

// round 8
// speedup vs baseline: 1.0009x; 1.0009x over previous
#include <cuda_runtime.h>
#include <cuda_bf16.h>
#include <cstdint>

// ---------------------------------------------------------------------------
// Swin window attention: B_=2048, N=49, H=16, D=32, C=512, nW=64, fp32.
// Split-bf16 HMMA GEMM: CTA 128x256, 3-stage cp.async, ONE sync per epoch.
// Conflict-free fused attention (unchanged from R6 winner).
// ---------------------------------------------------------------------------
#define B_TOT   2048
#define NTOK    49
#define NHEAD   16
#define HDIM    32
#define CDIM    512
#define NWIN    64
#define QK_SCALE 0.17677669529663687f
#define M_ROWS  (B_TOT * NTOK)          // 100352 = 784 * 128

__device__ float          g_qkv[(size_t)M_ROWS * 3 * CDIM];
__device__ __nv_bfloat16  g_xh [(size_t)M_ROWS * CDIM];
__device__ __nv_bfloat16  g_xl [(size_t)M_ROWS * CDIM];
__device__ __nv_bfloat16  g_aoh[(size_t)M_ROWS * CDIM];
__device__ __nv_bfloat16  g_aol[(size_t)M_ROWS * CDIM];
__device__ __nv_bfloat16  g_wqh[3 * CDIM * CDIM];
__device__ __nv_bfloat16  g_wql[3 * CDIM * CDIM];
__device__ __nv_bfloat16  g_wph[CDIM * CDIM];
__device__ __nv_bfloat16  g_wpl[CDIM * CDIM];

// ---------------------------------------------------------------------------
__device__ __forceinline__ uint32_t smem_u32(const void* p) {
    uint32_t a;
    asm("{ .reg .u64 t; cvta.to.shared.u64 t, %1; cvt.u32.u64 %0, t; }"
        : "=r"(a) : "l"(p));
    return a;
}

__device__ __forceinline__ void cvt_pair(float x, float y, uint32_t& hp, uint32_t& lp) {
    unsigned short h0 = __bfloat16_as_ushort(__float2bfloat16_rn(x));
    unsigned short h1 = __bfloat16_as_ushort(__float2bfloat16_rn(y));
    hp = (uint32_t)h0 | ((uint32_t)h1 << 16);
    float l0 = x - __uint_as_float((uint32_t)h0 << 16);
    float l1 = y - __uint_as_float((uint32_t)h1 << 16);
    asm("cvt.rn.bf16x2.f32 %0, %1, %2;" : "=r"(lp) : "f"(l1), "f"(l0));
}

#define LDSM4(r, addr) \
    asm volatile("ldmatrix.sync.aligned.m8n8.x4.shared.b16 {%0,%1,%2,%3}, [%4];" \
        : "=r"((r)[0]), "=r"((r)[1]), "=r"((r)[2]), "=r"((r)[3]) : "r"(addr))

#define MMA16816(d, a, b0, b1) \
    asm volatile("mma.sync.aligned.m16n8k16.row.col.f32.bf16.bf16.f32 " \
        "{%0,%1,%2,%3}, {%4,%5,%6,%7}, {%8,%9}, {%0,%1,%2,%3};" \
        : "+f"((d)[0]), "+f"((d)[1]), "+f"((d)[2]), "+f"((d)[3]) \
        : "r"((a)[0]), "r"((a)[1]), "r"((a)[2]), "r"((a)[3]), "r"(b0), "r"(b1))

#define CP16(saddr, gaddr) \
    asm volatile("cp.async.cg.shared.global [%0], [%1], 16;" :: "r"(saddr), "l"(gaddr))
#define CP_COMMIT() asm volatile("cp.async.commit_group;" ::: "memory")
#define CP_WAIT(n)  asm volatile("cp.async.wait_group %0;" :: "n"(n) : "memory")

// ---------------------------------------------------------------------------
__global__ void split_bf16_kernel(const float4* __restrict__ src,
                                  uint2* __restrict__ dh, uint2* __restrict__ dl,
                                  int n4)
{
    int i = blockIdx.x * blockDim.x + threadIdx.x;
    if (i < n4) {
        float4 v = src[i];
        uint32_t h0, l0, h1, l1;
        cvt_pair(v.x, v.y, h0, l0);
        cvt_pair(v.z, v.w, h1, l1);
        dh[i] = make_uint2(h0, h1);
        dl[i] = make_uint2(l0, l1);
    }
}

// ---------------------------------------------------------------------------
// HMMA split-bf16 GEMM: C[M,N] = A[M,K]*W[N,K]^T + bias.
// CTA 128(M) x 256(N), BK=32, 256 threads, 8 warps (2m x 4n), warp 64x64.
// 3-stage cp.async ring, ONE __syncthreads per K-epoch:
//   iter i: wait(stage i); sync; issue(stage i+2 -> buf (i+2)%3, last read by
//   compute(i-1) which finished before this sync); compute(i).
// smem rows: 32 bf16 payload (64B), 80B stride (conflict-free ldmatrix).
// ---------------------------------------------------------------------------
#define ROWB       80
#define A_TILE     10240           // 128 rows * 80B
#define B_TILE     20480           // 256 rows * 80B
#define STAGE_SZ   61440           // AH AL BH BL
#define SMEM_GEMM  184320          // 3 stages

__global__ __launch_bounds__(256, 1)
void hmma_gemm(const __nv_bfloat16* __restrict__ Ah, const __nv_bfloat16* __restrict__ Al,
               const __nv_bfloat16* __restrict__ Bh, const __nv_bfloat16* __restrict__ Bl,
               const float* __restrict__ bias, float* __restrict__ C,
               int N, int K)
{
    extern __shared__ char sm[];
    const uint32_t sb = smem_u32(sm);

    const int tid = threadIdx.x;
    const int wid = tid >> 5, lid = tid & 31;
    const int warp_m = wid & 1;          // 2 warps over M (64 each)
    const int warp_n = wid >> 1;         // 4 warps over N (64 each)
    const int m0 = blockIdx.y * 128;
    const int n0 = blockIdx.x * 256;

    const __nv_bfloat16* gA[2] = { Ah + (size_t)m0 * K, Al + (size_t)m0 * K };
    const __nv_bfloat16* gB[2] = { Bh + (size_t)n0 * K, Bl + (size_t)n0 * K };

    const uint32_t aRow  = (uint32_t)(warp_m * 64 + (lid & 15));
    const uint32_t aKoff = (uint32_t)((lid >> 4) << 4);
    const uint32_t bRow  = (uint32_t)(warp_n * 64 + ((lid >> 4) << 3) + (lid & 7));
    const uint32_t bKoff = (uint32_t)(((lid >> 3) & 1) << 4);
    const uint32_t aOff = aRow * ROWB + aKoff;
    const uint32_t bOff = bRow * ROWB + bKoff;

    float acc[4][8][4];
#pragma unroll
    for (int i = 0; i < 4; i++)
#pragma unroll
        for (int j = 0; j < 8; j++)
#pragma unroll
            for (int e = 0; e < 4; e++) acc[i][j][e] = 0.f;

    const int iters = K >> 5;      // BK=32

    // 3072 16B-chunks per stage: A hi/lo 512 each, B hi/lo 1024 each.
#define ISSUE_STAGE(it) do {                                                  \
        const int kblk = (it) * 32;                                           \
        const uint32_t stb = sb + ((it) % 3) * STAGE_SZ;                      \
        _Pragma("unroll")                                                     \
        for (int s = 0; s < 12; s++) {                                        \
            const int id = tid + s * 256;                                     \
            if (id < 1024) {                                                  \
                const int t = id >> 9, row = (id >> 2) & 127, c = id & 3;     \
                CP16(stb + t * A_TILE + row * ROWB + c * 16,                  \
                     gA[t] + (size_t)row * K + kblk + c * 8);                 \
            } else {                                                          \
                const int id2 = id - 1024;                                    \
                const int t = id2 >> 10, row = (id2 >> 2) & 255, c = id2 & 3; \
                CP16(stb + 2 * A_TILE + t * B_TILE + row * ROWB + c * 16,     \
                     gB[t] + (size_t)row * K + kblk + c * 8);                 \
            }                                                                 \
        }                                                                     \
    } while (0)

    ISSUE_STAGE(0); CP_COMMIT();
    ISSUE_STAGE(1); CP_COMMIT();

    for (int i = 0; i < iters; i++) {
        if (i + 1 < iters) CP_WAIT(1); else CP_WAIT(0);
        __syncthreads();                 // compute(i-1) done in ALL warps
        if (i + 2 < iters) { ISSUE_STAGE(i + 2); CP_COMMIT(); }

        const uint32_t st = sb + (i % 3) * STAGE_SZ;
        const uint32_t aHi = st + aOff;
        const uint32_t aLo = st + A_TILE + aOff;
        const uint32_t bHi = st + 2 * A_TILE + bOff;
        const uint32_t bLo = st + 2 * A_TILE + B_TILE + bOff;

#pragma unroll
        for (int ks = 0; ks < 2; ks++) {
            const uint32_t ko = (uint32_t)(ks * 32);
            uint32_t bh[4][4], bl[4][4];
#pragma unroll
            for (int p = 0; p < 4; p++) {
                LDSM4(bh[p], bHi + ko + p * (16 * ROWB));
                LDSM4(bl[p], bLo + ko + p * (16 * ROWB));
            }
#pragma unroll
            for (int mi = 0; mi < 4; mi++) {
                uint32_t ah[4], al[4];
                LDSM4(ah, aHi + ko + mi * (16 * ROWB));
                LDSM4(al, aLo + ko + mi * (16 * ROWB));
#pragma unroll
                for (int nj = 0; nj < 8; nj++) {
                    const uint32_t* bph = bh[nj >> 1] + ((nj & 1) << 1);
                    const uint32_t* bpl = bl[nj >> 1] + ((nj & 1) << 1);
                    MMA16816(acc[mi][nj], ah, bph[0], bph[1]);
                    MMA16816(acc[mi][nj], ah, bpl[0], bpl[1]);
                    MMA16816(acc[mi][nj], al, bph[0], bph[1]);
                }
            }
        }
    }
#undef ISSUE_STAGE

    const int l4 = lid >> 2;
    const int lc = (lid & 3) * 2;
#pragma unroll
    for (int mi = 0; mi < 4; mi++) {
        const int row = m0 + warp_m * 64 + mi * 16 + l4;
#pragma unroll
        for (int nj = 0; nj < 8; nj++) {
            const int col = n0 + warp_n * 64 + nj * 8 + lc;
            const float b0 = bias[col], b1 = bias[col + 1];
            float2 v0 = make_float2(acc[mi][nj][0] + b0, acc[mi][nj][1] + b1);
            float2 v1 = make_float2(acc[mi][nj][2] + b0, acc[mi][nj][3] + b1);
            *(float2*)(C + (size_t)row * N + col)       = v0;
            *(float2*)(C + (size_t)(row + 8) * N + col) = v1;
        }
    }
}

// ---------------------------------------------------------------------------
// Fused window attention, conflict-free mappings (R6 winner, unchanged).
// ---------------------------------------------------------------------------
#define SCPAD 68

__global__ __launch_bounds__(128)
void window_attn_kernel(const float* __restrict__ qkv,
                        const float* __restrict__ mask,
                        const float* __restrict__ rpb,
                        __nv_bfloat16* __restrict__ aoh,
                        __nv_bfloat16* __restrict__ aol)
{
    const int b = blockIdx.x >> 4;
    const int h = blockIdx.x & 15;
    const int tid = threadIdx.x;
    const int wid = tid >> 5, lid = tid & 31;

    __shared__ float qs[56][36];
    __shared__ float ks[64][36];
    __shared__ float vs[64][36];
    __shared__ float sc[56][SCPAD];

    const size_t base = (size_t)b * NTOK * (3 * CDIM) + h * HDIM;
    for (int idx = tid; idx < NTOK * HDIM; idx += 128) {
        const int n = idx >> 5, d = idx & 31;
        const size_t off = base + (size_t)n * (3 * CDIM) + d;
        qs[n][d] = qkv[off] * QK_SCALE;
        ks[n][d] = qkv[off + CDIM];
        vs[n][d] = qkv[off + 2 * CDIM];
    }
    for (int idx = tid; idx < 15 * HDIM; idx += 128) {
        const int n = NTOK + (idx >> 5), d = idx & 31;
        if (n < 56) qs[n][d] = 0.f;
        ks[n][d] = 0.f;
        vs[n][d] = 0.f;
    }
    __syncthreads();

    const float* mrow = mask + (size_t)(b & (NWIN - 1)) * NTOK * NTOK;
    {
        const int nt = tid & 7;
        const int mt = tid >> 3;
        float a[7][4];
#pragma unroll
        for (int i = 0; i < 7; i++)
#pragma unroll
            for (int j = 0; j < 4; j++) a[i][j] = 0.f;

#pragma unroll
        for (int d4 = 0; d4 < 8; d4++) {
            float4 k4[4];
#pragma unroll
            for (int j = 0; j < 4; j++) k4[j] = *(float4*)&ks[mt * 4 + j][d4 * 4];
#pragma unroll
            for (int i = 0; i < 7; i++) {
                float4 q4 = *(float4*)&qs[nt * 7 + i][d4 * 4];
#pragma unroll
                for (int j = 0; j < 4; j++)
                    a[i][j] += q4.x * k4[j].x + q4.y * k4[j].y
                             + q4.z * k4[j].z + q4.w * k4[j].w;
            }
        }
#pragma unroll
        for (int i = 0; i < 7; i++) {
            const int n = nt * 7 + i;
#pragma unroll
            for (int j = 0; j < 4; j++) {
                const int m = mt * 4 + j;
                float v;
                if (n < NTOK && m < NTOK) {
                    const int ridx = (n / 7 - m / 7 + 6) * 13 + (n % 7 - m % 7 + 6);
                    v = a[i][j] + rpb[ridx * NHEAD + h] + mrow[n * NTOK + m];
                } else {
                    v = (n < NTOK) ? -3.0e38f : 0.f;
                }
                sc[n][m] = v;
            }
        }
    }
    __syncthreads();

    for (int r = wid; r < NTOK; r += 4) {
        float v0 = sc[r][lid];
        float v1 = sc[r][lid + 32];
        float mx = fmaxf(v0, v1);
#pragma unroll
        for (int o = 16; o; o >>= 1) mx = fmaxf(mx, __shfl_xor_sync(~0u, mx, o));
        float e0 = __expf(v0 - mx);
        float e1 = __expf(v1 - mx);
        float s = e0 + e1;
#pragma unroll
        for (int o = 16; o; o >>= 1) s += __shfl_xor_sync(~0u, s, o);
        const float inv = 1.f / s;
        sc[r][lid] = e0 * inv;
        sc[r][lid + 32] = e1 * inv;
    }
    __syncthreads();

    {
        const int dp = tid & 15;
        const int nb = tid >> 4;
        float ac[7][2];
#pragma unroll
        for (int i = 0; i < 7; i++) { ac[i][0] = 0.f; ac[i][1] = 0.f; }

#pragma unroll
        for (int m4 = 0; m4 < 16; m4++) {
            float2 v2[4];
#pragma unroll
            for (int k = 0; k < 4; k++) v2[k] = *(float2*)&vs[m4 * 4 + k][dp * 2];
#pragma unroll
            for (int i = 0; i < 7; i++) {
                float4 s4 = *(float4*)&sc[nb + 8 * i][m4 * 4];
                ac[i][0] += s4.x * v2[0].x + s4.y * v2[1].x
                          + s4.z * v2[2].x + s4.w * v2[3].x;
                ac[i][1] += s4.x * v2[0].y + s4.y * v2[1].y
                          + s4.z * v2[2].y + s4.w * v2[3].y;
            }
        }
#pragma unroll
        for (int i = 0; i < 7; i++) {
            const int n = nb + 8 * i;
            if (n < NTOK) {
                const size_t o = (size_t)(b * NTOK + n) * CDIM + h * HDIM + dp * 2;
                uint32_t hp, lp;
                cvt_pair(ac[i][0], ac[i][1], hp, lp);
                *(uint32_t*)(aoh + o) = hp;
                *(uint32_t*)(aol + o) = lp;
            }
        }
    }
}

// ---------------------------------------------------------------------------
extern "C" void kernel_launch(void* const* d_in, const int* in_sizes, int n_in,
                              void* d_out, int out_size)
{
    const float* x      = (const float*)d_in[0];
    const float* mask   = (const float*)d_in[1];
    const float* rpb    = (const float*)d_in[2];
    const float* qkv_w  = (const float*)d_in[3];
    const float* qkv_b  = (const float*)d_in[4];
    const float* proj_w = (const float*)d_in[5];
    const float* proj_b = (const float*)d_in[6];
    float* out = (float*)d_out;

    float *qkv_ptr = nullptr;
    __nv_bfloat16 *xh, *xl, *aoh, *aol, *wqh, *wql, *wph, *wpl;
    cudaGetSymbolAddress((void**)&qkv_ptr, g_qkv);
    cudaGetSymbolAddress((void**)&xh,  g_xh);
    cudaGetSymbolAddress((void**)&xl,  g_xl);
    cudaGetSymbolAddress((void**)&aoh, g_aoh);
    cudaGetSymbolAddress((void**)&aol, g_aol);
    cudaGetSymbolAddress((void**)&wqh, g_wqh);
    cudaGetSymbolAddress((void**)&wql, g_wql);
    cudaGetSymbolAddress((void**)&wph, g_wph);
    cudaGetSymbolAddress((void**)&wpl, g_wpl);

    static bool cfg = false;
    if (!cfg) {
        cudaFuncSetAttribute(hmma_gemm, cudaFuncAttributeMaxDynamicSharedMemorySize,
                             SMEM_GEMM);
        cfg = true;
    }

    {
        int n4 = (M_ROWS * CDIM) / 4;
        split_bf16_kernel<<<(n4 + 255) / 256, 256>>>(
            (const float4*)x, (uint2*)xh, (uint2*)xl, n4);
        n4 = (3 * CDIM * CDIM) / 4;
        split_bf16_kernel<<<(n4 + 255) / 256, 256>>>(
            (const float4*)qkv_w, (uint2*)wqh, (uint2*)wql, n4);
        n4 = (CDIM * CDIM) / 4;
        split_bf16_kernel<<<(n4 + 255) / 256, 256>>>(
            (const float4*)proj_w, (uint2*)wph, (uint2*)wpl, n4);
    }

    // 1) QKV projection: grid (1536/256, 784)
    hmma_gemm<<<dim3((3 * CDIM) / 256, M_ROWS / 128), 256, SMEM_GEMM>>>(
        xh, xl, wqh, wql, qkv_b, qkv_ptr, 3 * CDIM, CDIM);

    // 2) Fused window attention
    window_attn_kernel<<<B_TOT * NHEAD, 128>>>(qkv_ptr, mask, rpb, aoh, aol);

    // 3) Output projection: grid (512/256, 784)
    hmma_gemm<<<dim3(CDIM / 256, M_ROWS / 128), 256, SMEM_GEMM>>>(
        aoh, aol, wph, wpl, proj_b, out, CDIM, CDIM);
}

// round 9
// speedup vs baseline: 1.0659x; 1.0649x over previous
#include <cuda_runtime.h>
#include <cuda_bf16.h>
#include <cstdint>

// ---------------------------------------------------------------------------
// Swin window attention: B_=2048, N=49, H=16, D=32, C=512, nW=64, fp32.
// Split-bf16 HMMA GEMM: CTA 128x128, 3-stage cp.async ring, ONE sync/epoch,
// packed 64B rows with chunk-rotation (conflict-free, 25% smem saved ->
// 2 CTAs/SM). Conflict-free fused attention (R6 winner, unchanged).
// ---------------------------------------------------------------------------
#define B_TOT   2048
#define NTOK    49
#define NHEAD   16
#define HDIM    32
#define CDIM    512
#define NWIN    64
#define QK_SCALE 0.17677669529663687f
#define M_ROWS  (B_TOT * NTOK)          // 100352 = 784 * 128

__device__ float          g_qkv[(size_t)M_ROWS * 3 * CDIM];
__device__ __nv_bfloat16  g_xh [(size_t)M_ROWS * CDIM];
__device__ __nv_bfloat16  g_xl [(size_t)M_ROWS * CDIM];
__device__ __nv_bfloat16  g_aoh[(size_t)M_ROWS * CDIM];
__device__ __nv_bfloat16  g_aol[(size_t)M_ROWS * CDIM];
__device__ __nv_bfloat16  g_wqh[3 * CDIM * CDIM];
__device__ __nv_bfloat16  g_wql[3 * CDIM * CDIM];
__device__ __nv_bfloat16  g_wph[CDIM * CDIM];
__device__ __nv_bfloat16  g_wpl[CDIM * CDIM];

// ---------------------------------------------------------------------------
__device__ __forceinline__ uint32_t smem_u32(const void* p) {
    uint32_t a;
    asm("{ .reg .u64 t; cvta.to.shared.u64 t, %1; cvt.u32.u64 %0, t; }"
        : "=r"(a) : "l"(p));
    return a;
}

__device__ __forceinline__ void cvt_pair(float x, float y, uint32_t& hp, uint32_t& lp) {
    unsigned short h0 = __bfloat16_as_ushort(__float2bfloat16_rn(x));
    unsigned short h1 = __bfloat16_as_ushort(__float2bfloat16_rn(y));
    hp = (uint32_t)h0 | ((uint32_t)h1 << 16);
    float l0 = x - __uint_as_float((uint32_t)h0 << 16);
    float l1 = y - __uint_as_float((uint32_t)h1 << 16);
    asm("cvt.rn.bf16x2.f32 %0, %1, %2;" : "=r"(lp) : "f"(l1), "f"(l0));
}

#define LDSM4(r, addr) \
    asm volatile("ldmatrix.sync.aligned.m8n8.x4.shared.b16 {%0,%1,%2,%3}, [%4];" \
        : "=r"((r)[0]), "=r"((r)[1]), "=r"((r)[2]), "=r"((r)[3]) : "r"(addr))

#define MMA16816(d, a, b0, b1) \
    asm volatile("mma.sync.aligned.m16n8k16.row.col.f32.bf16.bf16.f32 " \
        "{%0,%1,%2,%3}, {%4,%5,%6,%7}, {%8,%9}, {%0,%1,%2,%3};" \
        : "+f"((d)[0]), "+f"((d)[1]), "+f"((d)[2]), "+f"((d)[3]) \
        : "r"((a)[0]), "r"((a)[1]), "r"((a)[2]), "r"((a)[3]), "r"(b0), "r"(b1))

#define CP16(saddr, gaddr) \
    asm volatile("cp.async.cg.shared.global [%0], [%1], 16;" :: "r"(saddr), "l"(gaddr))
#define CP_COMMIT() asm volatile("cp.async.commit_group;" ::: "memory")
#define CP_WAIT(n)  asm volatile("cp.async.wait_group %0;" :: "n"(n) : "memory")

// ---------------------------------------------------------------------------
__global__ void split_bf16_kernel(const float4* __restrict__ src,
                                  uint2* __restrict__ dh, uint2* __restrict__ dl,
                                  int n4)
{
    int i = blockIdx.x * blockDim.x + threadIdx.x;
    if (i < n4) {
        float4 v = src[i];
        uint32_t h0, l0, h1, l1;
        cvt_pair(v.x, v.y, h0, l0);
        cvt_pair(v.z, v.w, h1, l1);
        dh[i] = make_uint2(h0, h1);
        dl[i] = make_uint2(l0, l1);
    }
}

// ---------------------------------------------------------------------------
// HMMA split-bf16 GEMM: C[M,N] = A[M,K]*W[N,K]^T + bias.
// CTA 128x128, BK=32, 256 threads, 8 warps (2m x 4n), warp tile 64x32.
// Packed rows: 64B/row, 16B chunk (r,c) at r*64 + ((c + (r>>1 & 3))&3)*16.
//   8-row-aligned ldmatrix phases hit 8 distinct bank-quads -> conflict-free;
//   cp.async writes likewise. 25% smem smaller than 80B-pad -> 3 stages fit
//   at 2 CTAs/SM.
// 3-stage ring, ONE __syncthreads per K-epoch.
// ---------------------------------------------------------------------------
#define TILE_SZ   8192             // 128 rows * 64B
#define STAGE_SZ  32768            // AH AL BH BL
#define SMEM_GEMM 98304            // 3 stages

__global__ __launch_bounds__(256, 2)
void hmma_gemm(const __nv_bfloat16* __restrict__ Ah, const __nv_bfloat16* __restrict__ Al,
               const __nv_bfloat16* __restrict__ Bh, const __nv_bfloat16* __restrict__ Bl,
               const float* __restrict__ bias, float* __restrict__ C,
               int N, int K)
{
    extern __shared__ char sm[];
    const uint32_t sb = smem_u32(sm);

    const int tid = threadIdx.x;
    const int wid = tid >> 5, lid = tid & 31;
    const int warp_m = wid & 1;
    const int warp_n = wid >> 1;
    const int m0 = blockIdx.y * 128;
    const int n0 = blockIdx.x * 128;

    const __nv_bfloat16* gbase[4] = {
        Ah + (size_t)m0 * K, Al + (size_t)m0 * K,
        Bh + (size_t)n0 * K, Bl + (size_t)n0 * K };

    // ldmatrix lane addresses under rotation layout (per ks-step: chunks 2ks+c)
    const uint32_t aRowL = (uint32_t)(warp_m * 64 + (lid & 15));
    const uint32_t ac    = (uint32_t)(lid >> 4);            // 0..1
    const uint32_t arot  = (aRowL >> 1) & 3;
    const uint32_t aO[2] = { aRowL * 64 + ((ac + arot) & 3) * 16,
                             aRowL * 64 + ((ac + 2 + arot) & 3) * 16 };
    const uint32_t bRowL = (uint32_t)(warp_n * 32 + ((lid >> 4) << 3) + (lid & 7));
    const uint32_t bc    = (uint32_t)((lid >> 3) & 1);
    const uint32_t brot  = (bRowL >> 1) & 3;
    const uint32_t bO[2] = { bRowL * 64 + ((bc + brot) & 3) * 16,
                             bRowL * 64 + ((bc + 2 + brot) & 3) * 16 };

    float acc[4][4][4];
#pragma unroll
    for (int i = 0; i < 4; i++)
#pragma unroll
        for (int j = 0; j < 4; j++)
#pragma unroll
            for (int e = 0; e < 4; e++) acc[i][j][e] = 0.f;

    const int iters = K >> 5;      // BK=32

    // 2048 16B chunks/stage, 8 per thread; rotated chunk placement.
#define ISSUE_STAGE(it) do {                                                  \
        const int kblk = (it) * 32;                                           \
        const uint32_t stb = sb + ((it) % 3) * STAGE_SZ;                      \
        _Pragma("unroll")                                                     \
        for (int s = 0; s < 8; s++) {                                         \
            const int id   = tid + s * 256;                                   \
            const int tile = id >> 9;                                         \
            const int row  = (id >> 2) & 127;                                 \
            const int c    = id & 3;                                          \
            const int cc   = (c + ((row >> 1) & 3)) & 3;                      \
            CP16(stb + tile * TILE_SZ + row * 64 + cc * 16,                   \
                 gbase[tile] + (size_t)row * K + kblk + c * 8);               \
        }                                                                     \
    } while (0)

    ISSUE_STAGE(0); CP_COMMIT();
    ISSUE_STAGE(1); CP_COMMIT();

    for (int i = 0; i < iters; i++) {
        if (i + 1 < iters) CP_WAIT(1); else CP_WAIT(0);
        __syncthreads();               // all warps done with compute(i-1)
        if (i + 2 < iters) { ISSUE_STAGE(i + 2); CP_COMMIT(); }
        // stage i+2 -> buf (i+2)%3, last read by compute(i-1): safe after sync

        const uint32_t st  = sb + (i % 3) * STAGE_SZ;
        const uint32_t aHi = st;
        const uint32_t aLo = st + TILE_SZ;
        const uint32_t bHi = st + 2 * TILE_SZ;
        const uint32_t bLo = st + 3 * TILE_SZ;

#pragma unroll
        for (int ks = 0; ks < 2; ks++) {
            uint32_t bh[2][4], bl[2][4];
            LDSM4(bh[0], bHi + bO[ks]);
            LDSM4(bh[1], bHi + bO[ks] + 16 * 64);
            LDSM4(bl[0], bLo + bO[ks]);
            LDSM4(bl[1], bLo + bO[ks] + 16 * 64);
#pragma unroll
            for (int mi = 0; mi < 4; mi++) {
                uint32_t ah[4], al[4];
                LDSM4(ah, aHi + aO[ks] + mi * (16 * 64));
                LDSM4(al, aLo + aO[ks] + mi * (16 * 64));
#pragma unroll
                for (int nj = 0; nj < 4; nj++) {
                    const uint32_t* bph = bh[nj >> 1] + ((nj & 1) << 1);
                    const uint32_t* bpl = bl[nj >> 1] + ((nj & 1) << 1);
                    MMA16816(acc[mi][nj], ah, bph[0], bph[1]);
                    MMA16816(acc[mi][nj], ah, bpl[0], bpl[1]);
                    MMA16816(acc[mi][nj], al, bph[0], bph[1]);
                }
            }
        }
    }
#undef ISSUE_STAGE

    const int l4 = lid >> 2;
    const int lc = (lid & 3) * 2;
#pragma unroll
    for (int mi = 0; mi < 4; mi++) {
        const int row = m0 + warp_m * 64 + mi * 16 + l4;
#pragma unroll
        for (int nj = 0; nj < 4; nj++) {
            const int col = n0 + warp_n * 32 + nj * 8 + lc;
            const float b0 = bias[col], b1 = bias[col + 1];
            float2 v0 = make_float2(acc[mi][nj][0] + b0, acc[mi][nj][1] + b1);
            float2 v1 = make_float2(acc[mi][nj][2] + b0, acc[mi][nj][3] + b1);
            *(float2*)(C + (size_t)row * N + col)       = v0;
            *(float2*)(C + (size_t)(row + 8) * N + col) = v1;
        }
    }
}

// ---------------------------------------------------------------------------
// Fused window attention, conflict-free mappings (R6 winner, unchanged).
// ---------------------------------------------------------------------------
#define SCPAD 68

__global__ __launch_bounds__(128)
void window_attn_kernel(const float* __restrict__ qkv,
                        const float* __restrict__ mask,
                        const float* __restrict__ rpb,
                        __nv_bfloat16* __restrict__ aoh,
                        __nv_bfloat16* __restrict__ aol)
{
    const int b = blockIdx.x >> 4;
    const int h = blockIdx.x & 15;
    const int tid = threadIdx.x;
    const int wid = tid >> 5, lid = tid & 31;

    __shared__ float qs[56][36];
    __shared__ float ks[64][36];
    __shared__ float vs[64][36];
    __shared__ float sc[56][SCPAD];

    const size_t base = (size_t)b * NTOK * (3 * CDIM) + h * HDIM;
    for (int idx = tid; idx < NTOK * HDIM; idx += 128) {
        const int n = idx >> 5, d = idx & 31;
        const size_t off = base + (size_t)n * (3 * CDIM) + d;
        qs[n][d] = qkv[off] * QK_SCALE;
        ks[n][d] = qkv[off + CDIM];
        vs[n][d] = qkv[off + 2 * CDIM];
    }
    for (int idx = tid; idx < 15 * HDIM; idx += 128) {
        const int n = NTOK + (idx >> 5), d = idx & 31;
        if (n < 56) qs[n][d] = 0.f;
        ks[n][d] = 0.f;
        vs[n][d] = 0.f;
    }
    __syncthreads();

    const float* mrow = mask + (size_t)(b & (NWIN - 1)) * NTOK * NTOK;
    {
        const int nt = tid & 7;
        const int mt = tid >> 3;
        float a[7][4];
#pragma unroll
        for (int i = 0; i < 7; i++)
#pragma unroll
            for (int j = 0; j < 4; j++) a[i][j] = 0.f;

#pragma unroll
        for (int d4 = 0; d4 < 8; d4++) {
            float4 k4[4];
#pragma unroll
            for (int j = 0; j < 4; j++) k4[j] = *(float4*)&ks[mt * 4 + j][d4 * 4];
#pragma unroll
            for (int i = 0; i < 7; i++) {
                float4 q4 = *(float4*)&qs[nt * 7 + i][d4 * 4];
#pragma unroll
                for (int j = 0; j < 4; j++)
                    a[i][j] += q4.x * k4[j].x + q4.y * k4[j].y
                             + q4.z * k4[j].z + q4.w * k4[j].w;
            }
        }
#pragma unroll
        for (int i = 0; i < 7; i++) {
            const int n = nt * 7 + i;
#pragma unroll
            for (int j = 0; j < 4; j++) {
                const int m = mt * 4 + j;
                float v;
                if (n < NTOK && m < NTOK) {
                    const int ridx = (n / 7 - m / 7 + 6) * 13 + (n % 7 - m % 7 + 6);
                    v = a[i][j] + rpb[ridx * NHEAD + h] + mrow[n * NTOK + m];
                } else {
                    v = (n < NTOK) ? -3.0e38f : 0.f;
                }
                sc[n][m] = v;
            }
        }
    }
    __syncthreads();

    for (int r = wid; r < NTOK; r += 4) {
        float v0 = sc[r][lid];
        float v1 = sc[r][lid + 32];
        float mx = fmaxf(v0, v1);
#pragma unroll
        for (int o = 16; o; o >>= 1) mx = fmaxf(mx, __shfl_xor_sync(~0u, mx, o));
        float e0 = __expf(v0 - mx);
        float e1 = __expf(v1 - mx);
        float s = e0 + e1;
#pragma unroll
        for (int o = 16; o; o >>= 1) s += __shfl_xor_sync(~0u, s, o);
        const float inv = 1.f / s;
        sc[r][lid] = e0 * inv;
        sc[r][lid + 32] = e1 * inv;
    }
    __syncthreads();

    {
        const int dp = tid & 15;
        const int nb = tid >> 4;
        float ac[7][2];
#pragma unroll
        for (int i = 0; i < 7; i++) { ac[i][0] = 0.f; ac[i][1] = 0.f; }

#pragma unroll
        for (int m4 = 0; m4 < 16; m4++) {
            float2 v2[4];
#pragma unroll
            for (int k = 0; k < 4; k++) v2[k] = *(float2*)&vs[m4 * 4 + k][dp * 2];
#pragma unroll
            for (int i = 0; i < 7; i++) {
                float4 s4 = *(float4*)&sc[nb + 8 * i][m4 * 4];
                ac[i][0] += s4.x * v2[0].x + s4.y * v2[1].x
                          + s4.z * v2[2].x + s4.w * v2[3].x;
                ac[i][1] += s4.x * v2[0].y + s4.y * v2[1].y
                          + s4.z * v2[2].y + s4.w * v2[3].y;
            }
        }
#pragma unroll
        for (int i = 0; i < 7; i++) {
            const int n = nb + 8 * i;
            if (n < NTOK) {
                const size_t o = (size_t)(b * NTOK + n) * CDIM + h * HDIM + dp * 2;
                uint32_t hp, lp;
                cvt_pair(ac[i][0], ac[i][1], hp, lp);
                *(uint32_t*)(aoh + o) = hp;
                *(uint32_t*)(aol + o) = lp;
            }
        }
    }
}

// ---------------------------------------------------------------------------
extern "C" void kernel_launch(void* const* d_in, const int* in_sizes, int n_in,
                              void* d_out, int out_size)
{
    const float* x      = (const float*)d_in[0];
    const float* mask   = (const float*)d_in[1];
    const float* rpb    = (const float*)d_in[2];
    const float* qkv_w  = (const float*)d_in[3];
    const float* qkv_b  = (const float*)d_in[4];
    const float* proj_w = (const float*)d_in[5];
    const float* proj_b = (const float*)d_in[6];
    float* out = (float*)d_out;

    float *qkv_ptr = nullptr;
    __nv_bfloat16 *xh, *xl, *aoh, *aol, *wqh, *wql, *wph, *wpl;
    cudaGetSymbolAddress((void**)&qkv_ptr, g_qkv);
    cudaGetSymbolAddress((void**)&xh,  g_xh);
    cudaGetSymbolAddress((void**)&xl,  g_xl);
    cudaGetSymbolAddress((void**)&aoh, g_aoh);
    cudaGetSymbolAddress((void**)&aol, g_aol);
    cudaGetSymbolAddress((void**)&wqh, g_wqh);
    cudaGetSymbolAddress((void**)&wql, g_wql);
    cudaGetSymbolAddress((void**)&wph, g_wph);
    cudaGetSymbolAddress((void**)&wpl, g_wpl);

    static bool cfg = false;
    if (!cfg) {
        cudaFuncSetAttribute(hmma_gemm, cudaFuncAttributeMaxDynamicSharedMemorySize,
                             SMEM_GEMM);
        cfg = true;
    }

    {
        int n4 = (M_ROWS * CDIM) / 4;
        split_bf16_kernel<<<(n4 + 255) / 256, 256>>>(
            (const float4*)x, (uint2*)xh, (uint2*)xl, n4);
        n4 = (3 * CDIM * CDIM) / 4;
        split_bf16_kernel<<<(n4 + 255) / 256, 256>>>(
            (const float4*)qkv_w, (uint2*)wqh, (uint2*)wql, n4);
        n4 = (CDIM * CDIM) / 4;
        split_bf16_kernel<<<(n4 + 255) / 256, 256>>>(
            (const float4*)proj_w, (uint2*)wph, (uint2*)wpl, n4);
    }

    // 1) QKV projection: grid (1536/128, 784)
    hmma_gemm<<<dim3((3 * CDIM) / 128, M_ROWS / 128), 256, SMEM_GEMM>>>(
        xh, xl, wqh, wql, qkv_b, qkv_ptr, 3 * CDIM, CDIM);

    // 2) Fused window attention
    window_attn_kernel<<<B_TOT * NHEAD, 128>>>(qkv_ptr, mask, rpb, aoh, aol);

    // 3) Output projection: grid (512/128, 784)
    hmma_gemm<<<dim3(CDIM / 128, M_ROWS / 128), 256, SMEM_GEMM>>>(
        aoh, aol, wph, wpl, proj_b, out, CDIM, CDIM);
}